// round 14
// baseline (speedup 1.0000x reference)
#include <cuda_runtime.h>
#include <cstdint>
#include <math.h>

// ---- problem constants ----
#define NPK   10
#define LLEN  14
#define EMB   128
#define HH    160
#define WW    160
#define NBC   32
#define NGRID 36
#define NPOS  (NGRID*NGRID)
#define NUNIT (NPOS*NBC)    // 41472
#define NROW  (NUNIT*NPK)   // 414720
#define SEV   0x07070707
#define ONES  0x01010101

// ---- static scratch ----
__device__ float g_patches[(size_t)NROW * 49];
__device__ float g_den[(size_t)NROW * 49];
__device__ int4  g_cp[NUNIT * 2];   // [2u]=x-bytes(10+2 pad 0xC8), [2u+1]=y-bytes
__device__ float g_Wc[49 * 52];
__device__ float g_bias[NPK * 49];

// ============================================================
// K0: fold projections, ILP-4 (R13-measured)
// ============================================================
__global__ void prep_kernel(const float* __restrict__ Wp, const float* __restrict__ bp,
                            const float* __restrict__ pe, const float* __restrict__ Wb,
                            const float* __restrict__ bb) {
    int i = blockIdx.x * blockDim.x + threadIdx.x;
    if (i < 49 * 49) {
        int q = i / 49, k = i % 49;
        float s0 = 0.0f, s1 = 0.0f, s2 = 0.0f, s3 = 0.0f;
        #pragma unroll 8
        for (int e = 0; e < EMB; e += 4) {
            s0 = fmaf(Wp[q * EMB + e],     Wb[(e)     * 49 + k], s0);
            s1 = fmaf(Wp[q * EMB + e + 1], Wb[(e + 1) * 49 + k], s1);
            s2 = fmaf(Wp[q * EMB + e + 2], Wb[(e + 2) * 49 + k], s2);
            s3 = fmaf(Wp[q * EMB + e + 3], Wb[(e + 3) * 49 + k], s3);
        }
        g_Wc[q * 52 + k] = (s0 + s1) + (s2 + s3);
    } else if (i < 49 * 49 + NPK * 49) {
        int j = i - 49 * 49;
        int n = j / 49, k = j % 49;
        float s0 = bb[k], s1 = 0.0f, s2 = 0.0f, s3 = 0.0f;
        #pragma unroll 8
        for (int e = 0; e < EMB; e += 4) {
            s0 = fmaf(bp[e]     + pe[n * EMB + e],     Wb[(e)     * 49 + k], s0);
            s1 = fmaf(bp[e + 1] + pe[n * EMB + e + 1], Wb[(e + 1) * 49 + k], s1);
            s2 = fmaf(bp[e + 2] + pe[n * EMB + e + 2], Wb[(e + 2) * 49 + k], s2);
            s3 = fmaf(bp[e + 3] + pe[n * EMB + e + 3], Wb[(e + 3) * 49 + k], s3);
        }
        g_bias[j] = (s0 + s1) + (s2 + s3);
    }
}

// ============================================================
// K1: sims + top-10 (REDUX, lax.top_k tie-break) + transposed
//     patches + byte-packed coords. (R13-measured)
// ============================================================
__global__ void __launch_bounds__(256) simtopk_kernel(const float* __restrict__ images) {
    __shared__ float swin_all[8][400];
    int wid = threadIdx.x >> 5, lane = threadIdx.x & 31;
    int unit = blockIdx.x * 8 + wid;
    float* swin = swin_all[wid];

    int p  = unit >> 5;
    int bc = unit & 31;
    int px = p / NGRID, py = p % NGRID;
    int x = px * 4, y = py * 4;
    int xb0 = x - 7; if (xb0 < 0) xb0 = 0;
    int yb0 = y - 7; if (yb0 < 0) yb0 = 0;
    int winW = x + 13 - xb0;
    int winH = y + 13 - yb0;

    const float* plane = images + (size_t)bc * (HH * WW);
    for (int t = lane; t < 400; t += 32)
        swin[t] = plane[(yb0 + t / 20) * WW + xb0 + (t % 20)];
    __syncwarp();

    int ry = y - yb0, rx = x - xb0;
    int r = lane >> 1, ox0 = (lane & 1) * 7;
    bool active = lane < 28;
    float acc[7];
    int flatbase;
    if (active) {
        #pragma unroll
        for (int o = 0; o < 7; o++) acc[o] = 0.0f;
        for (int a = 0; a < 7; a++) {
            float w[13];
            #pragma unroll
            for (int v = 0; v < 13; v++) w[v] = swin[(r + a) * 20 + ox0 + v];
            #pragma unroll
            for (int b = 0; b < 7; b++) {
                float rv = swin[(ry + a) * 20 + rx + b];
                #pragma unroll
                for (int o = 0; o < 7; o++) acc[o] = fmaf(w[o + b], rv, acc[o]);
            }
        }
        int maxr = winH - 7, maxc = winW - 7;
        #pragma unroll
        for (int o = 0; o < 7; o++)
            if (r > maxr || (ox0 + o) > maxc) acc[o] = -INFINITY;
        flatbase = r * LLEN + ox0;
    } else {
        #pragma unroll
        for (int o = 0; o < 7; o++) acc[o] = -INFINITY;
        flatbase = 1 << 20;
    }

    int lane_m7 = lane % 7, lane_d7 = lane / 7;
    int q32_m7 = (lane + 32) % 7, q32_d7 = (lane + 32) / 7;

    int xw0 = 0, xw1 = 0, xw2 = 0xC8C80000, yw0 = 0, yw1 = 0, yw2 = 0xC8C80000;

    for (int n = 0; n < NPK; n++) {
        float bv = acc[0]; int bo = 0;
        #pragma unroll
        for (int o = 1; o < 7; o++)
            if (acc[o] > bv) { bv = acc[o]; bo = o; }
        unsigned ub = __float_as_uint(bv);
        ub ^= (unsigned)(((int)ub >> 31)) | 0x80000000u;
        unsigned wmax = __reduce_max_sync(0xffffffffu, ub);
        int cand = (ub == wmax) ? (flatbase + bo) : 0x7fffffff;
        int bi = __reduce_min_sync(0xffffffffu, cand);

        if (active && bi >= flatbase && bi < flatbase + 7) acc[bi - flatbase] = -INFINITY;

        int oy = bi / LLEN, ox = bi - oy * LLEN;
        float* pout = g_patches + ((size_t)unit * NPK + n) * 49;
        pout[lane] = swin[(oy + lane_m7) * 20 + ox + lane_d7];
        if (lane < 17)
            pout[lane + 32] = swin[(oy + q32_m7) * 20 + ox + q32_d7];
        if (lane == 0) {
            int xb = oy + xb0, yb = ox + yb0;   // bug kept: x from row off, y from col off
            int sh = (n & 3) * 8;
            if (n < 4)      { xw0 |= xb << sh; yw0 |= yb << sh; }
            else if (n < 8) { xw1 |= xb << sh; yw1 |= yb << sh; }
            else            { xw2 |= xb << sh; yw2 |= yb << sh; }
        }
    }
    if (lane == 0) {
        g_cp[unit * 2]     = make_int4(xw0, xw1, xw2, 0);
        g_cp[unit * 2 + 1] = make_int4(yw0, yw1, yw2, 0);
    }
}

// ============================================================
// K2: den[row] = patches[row] @ Wc + bias[row % 10] (R13-measured)
// ============================================================
__global__ void __launch_bounds__(128) gemm_kernel() {
    __shared__ float s_pat[128 * 49];
    __shared__ float s_Wc[49 * 52];
    __shared__ float s_bias[NPK * 49];
    int t = threadIdx.x;
    size_t base = (size_t)blockIdx.x * 128 * 49;
    for (int i = t; i < 128 * 49; i += 128) s_pat[i] = g_patches[base + i];
    for (int i = t; i < 49 * 52;  i += 128) s_Wc[i]  = g_Wc[i];
    for (int i = t; i < NPK * 49; i += 128) s_bias[i] = g_bias[i];
    __syncthreads();

    int grow = blockIdx.x * 128 + t;
    int n = grow % NPK;
    float acc[49];
    #pragma unroll
    for (int k = 0; k < 49; k++) acc[k] = s_bias[n * 49 + k];
    for (int q = 0; q < 49; q++) {
        float pq = s_pat[t * 49 + q];
        #pragma unroll
        for (int k4 = 0; k4 < 12; k4++) {
            float4 w = *(const float4*)&s_Wc[q * 52 + k4 * 4];
            acc[k4 * 4 + 0] = fmaf(pq, w.x, acc[k4 * 4 + 0]);
            acc[k4 * 4 + 1] = fmaf(pq, w.y, acc[k4 * 4 + 1]);
            acc[k4 * 4 + 2] = fmaf(pq, w.z, acc[k4 * 4 + 2]);
            acc[k4 * 4 + 3] = fmaf(pq, w.w, acc[k4 * 4 + 3]);
        }
        acc[48] = fmaf(pq, s_Wc[q * 52 + 48], acc[48]);
    }
    __syncthreads();
    #pragma unroll
    for (int k = 0; k < 49; k++) s_pat[t * 49 + k] = acc[k];
    __syncthreads();
    for (int i = t; i < 128 * 49; i += 128) g_den[base + i] = s_pat[i];
}

// ============================================================
// K3: PAIR gather — each thread handles pixels (r,c) and (r,c+1).
// Shared coord loads; xdB = xdA + 1 per byte; yd shared for reads,
// xd shared for incs. Union ranges keep segment classification
// valid for both pixels; exact byte masks handle boundaries.
// Per-pixel affine state:
//   read at counter c : B = fma(d, W, B);  W *= (c+1)/c
//   k incs            : W *= c/(c+k)
//   final             : v = (v0 + B) * frcp(W * c_final)
// ============================================================
__device__ __forceinline__ void inc2_word(int xw, int yw, int cvec, int rvec,
                                          int& kA, int& kB) {
    int xd  = __vsub4(rvec, xw);                 // shared (row)
    int ydA = __vsub4(cvec, yw);
    int ydB = __vadd4((unsigned)ydA, ONES);
    unsigned mx = __vcmpltu4(xd, SEV);
    kA += __popc(mx & __vcmpltu4(ydA, SEV) & 0x01010101u);
    kB += __popc(mx & __vcmpltu4(ydB, SEV) & 0x01010101u);
}

__device__ __forceinline__ void inc2_pos(int pidx, int cvec, int rvec,
                                         int& kA, int& kB) {
    int4 xq = g_cp[pidx * 2];
    int4 yq = g_cp[pidx * 2 + 1];
    inc2_word(xq.x, yq.x, cvec, rvec, kA, kB);
    inc2_word(xq.y, yq.y, cvec, rvec, kA, kB);
    inc2_word(xq.z, yq.z, cvec, rvec, kA, kB);
}

__device__ __forceinline__ void read2_word(int xw, int yw, int n0, int sbase,
                                           int cvec, int rvec,
                                           float bwA, float& WA, float& BA,
                                           float bwB, float& WB, float& BB) {
    int xdA = __vsub4(cvec, xw);
    int xdB = __vadd4((unsigned)xdA, ONES);
    int yd  = __vsub4(rvec, yw);                 // shared (row)
    unsigned my = __vcmpltu4(yd, SEV);
    unsigned mA = __vcmpltu4(xdA, SEV) & my;
    unsigned mB = __vcmpltu4(xdB, SEV) & my;
    while (mA) {
        int sh = __ffs(mA) - 1;
        int n = n0 + (sh >> 3);
        float d = g_den[(size_t)(sbase + n) * 49 + ((yd >> sh) & 7) * 7 + ((xdA >> sh) & 7)];
        BA = fmaf(d, WA, BA);
        WA *= bwA;
        mA &= ~(0xFFu << sh);
    }
    while (mB) {
        int sh = __ffs(mB) - 1;
        int n = n0 + (sh >> 3);
        float d = g_den[(size_t)(sbase + n) * 49 + ((yd >> sh) & 7) * 7 + ((xdB >> sh) & 7)];
        BB = fmaf(d, WB, BB);
        WB *= bwB;
        mB &= ~(0xFFu << sh);
    }
}

__device__ __forceinline__ void read2_pos(int pidx, int cvec, int rvec,
                                          float bwA, float& WA, float& BA,
                                          float bwB, float& WB, float& BB) {
    int4 xq = g_cp[pidx * 2];
    int4 yq = g_cp[pidx * 2 + 1];
    int sbase = pidx * NPK;
    read2_word(xq.x, yq.x, 0, sbase, cvec, rvec, bwA, WA, BA, bwB, WB, BB);
    read2_word(xq.y, yq.y, 4, sbase, cvec, rvec, bwA, WA, BA, bwB, WB, BB);
    read2_word(xq.z, yq.z, 8, sbase, cvec, rvec, bwA, WA, BA, bwB, WB, BB);
}

__device__ __forceinline__ void mixed2_word(int xw, int yw, int n0, int sbase,
                                            int cvec, int rvec,
                                            int& cntA, float& bwA, float& WA, float& BA,
                                            int& cntB, float& bwB, float& WB, float& BB,
                                            const float* __restrict__ s_rcp) {
    int xdRA = __vsub4(cvec, xw);
    int xdRB = __vadd4((unsigned)xdRA, ONES);
    int ydR  = __vsub4(rvec, yw);
    unsigned myR = __vcmpltu4(ydR, SEV);
    unsigned mRA = __vcmpltu4(xdRA, SEV) & myR;
    unsigned mRB = __vcmpltu4(xdRB, SEV) & myR;
    int xdI  = __vsub4(rvec, xw);
    int ydIA = __vsub4(cvec, yw);
    int ydIB = __vadd4((unsigned)ydIA, ONES);
    unsigned mxI = __vcmpltu4(xdI, SEV);
    unsigned mIA = mxI & __vcmpltu4(ydIA, SEV);
    unsigned mIB = mxI & __vcmpltu4(ydIB, SEV);

    unsigned mo = mRA | mIA;
    while (mo) {
        int sh = __ffs(mo) - 1;
        if ((mRA >> sh) & 1) {
            int n = n0 + (sh >> 3);
            float d = g_den[(size_t)(sbase + n) * 49 + ((ydR >> sh) & 7) * 7 + ((xdRA >> sh) & 7)];
            BA = fmaf(d, WA, BA);
            WA *= bwA;
        }
        if ((mIA >> sh) & 1) {
            WA *= (1.0f - s_rcp[cntA + 1]);
            cntA++;
            bwA = 1.0f + s_rcp[cntA];
        }
        mo &= ~(0xFFu << sh);
    }
    mo = mRB | mIB;
    while (mo) {
        int sh = __ffs(mo) - 1;
        if ((mRB >> sh) & 1) {
            int n = n0 + (sh >> 3);
            float d = g_den[(size_t)(sbase + n) * 49 + ((ydR >> sh) & 7) * 7 + ((xdRB >> sh) & 7)];
            BB = fmaf(d, WB, BB);
            WB *= bwB;
        }
        if ((mIB >> sh) & 1) {
            WB *= (1.0f - s_rcp[cntB + 1]);
            cntB++;
            bwB = 1.0f + s_rcp[cntB];
        }
        mo &= ~(0xFFu << sh);
    }
}

__device__ __forceinline__ void mixed2_pos(int pidx, int cvec, int rvec,
                                           int& cntA, float& bwA, float& WA, float& BA,
                                           int& cntB, float& bwB, float& WB, float& BB,
                                           const float* __restrict__ s_rcp) {
    int4 xq = g_cp[pidx * 2];
    int4 yq = g_cp[pidx * 2 + 1];
    int sbase = pidx * NPK;
    mixed2_word(xq.x, yq.x, 0, sbase, cvec, rvec, cntA, bwA, WA, BA, cntB, bwB, WB, BB, s_rcp);
    mixed2_word(xq.y, yq.y, 4, sbase, cvec, rvec, cntA, bwA, WA, BA, cntB, bwB, WB, BB, s_rcp);
    mixed2_word(xq.z, yq.z, 8, sbase, cvec, rvec, cntA, bwA, WA, BA, cntB, bwB, WB, BB, s_rcp);
}

#define UPD2(cnt, bw, W, k) do { if (k) { \
    W *= (float)(cnt) * s_rcp[(cnt) + (k)]; (cnt) += (k); (bw) = 1.0f + s_rcp[(cnt)]; } } while (0)

__global__ void __launch_bounds__(256) gather_kernel(const float* __restrict__ images,
                                                     float* __restrict__ out) {
    __shared__ float s_rcp[512];
    {
        int t = threadIdx.y * 32 + threadIdx.x;
        for (int i = t; i < 512; i += 256) s_rcp[i] = __frcp_rn((float)i);  // 1/c
    }
    __syncthreads();

    int bc   = threadIdx.x;                     // lane = plane -> warp-uniform (r,c)
    int pix0 = blockIdx.x * 16 + threadIdx.y * 2;   // even column, pair in same row
    int r = pix0 / WW, c = pix0 % WW;

    const float* plane = images + (size_t)bc * (HH * WW);
    float v0A = plane[pix0];
    float v0B = plane[pix0 + 1];

    int lr = (r <= 19) ? 0 : ((r - 9) >> 2);
    int hr = (r + 7) >> 2; if (hr > 35) hr = 35;
    int lc = (c <= 19) ? 0 : ((c - 9) >> 2);              // lc(c) <= lc(c+1)
    int hc = (c + 8) >> 2; if (hc > 35) hc = 35;          // hc(c+1) union

    int cvec = c * ONES, rvec = r * ONES;
    float WA = 1.0f, BA = 0.0f, WB = 1.0f, BB = 0.0f;
    int cntA = 1, cntB = 1;

    if (hc < lr) {
        // all reads before any inc for both pixels: counter = 1, bw = 2
        for (int px = lc; px <= hc; ++px) {
            int pbase = (px * NGRID + lr) * NBC + bc;
            for (int py = lr; py <= hr; ++py, pbase += NBC)
                read2_pos(pbase, cvec, rvec, 2.0f, WA, BA, 2.0f, WB, BB);
        }
    } else if (hr < lc) {
        // all incs before all reads for both pixels
        int TA = 0, TB = 0;
        for (int px = lr; px <= hr; ++px) {
            int pbase = (px * NGRID + lc) * NBC + bc;
            for (int py = lc; py <= hc; ++py, pbase += NBC)
                inc2_pos(pbase, cvec, rvec, TA, TB);
        }
        cntA = 1 + TA; cntB = 1 + TB;
        WA = s_rcp[cntA]; WB = s_rcp[cntB];
        float bwA = 1.0f + s_rcp[cntA], bwB = 1.0f + s_rcp[cntB];
        for (int px = lc; px <= hc; ++px) {
            int pbase = (px * NGRID + lr) * NBC + bc;
            for (int py = lr; py <= hr; ++py, pbase += NBC)
                read2_pos(pbase, cvec, rvec, bwA, WA, BA, bwB, WB, BB);
        }
    } else {
        // general segmented walk over union ranges
        float bwA = 2.0f, bwB = 2.0f;
        int a = max(lr, lc), b = min(hr, hc);

        if (lc < lr) {
            for (int px = lc; px < a; ++px) {
                int pbase = (px * NGRID + lr) * NBC + bc;
                for (int py = lr; py <= hr; ++py, pbase += NBC)
                    read2_pos(pbase, cvec, rvec, bwA, WA, BA, bwB, WB, BB);
            }
        } else if (lr < lc) {
            int kA = 0, kB = 0;
            for (int px = lr; px < a; ++px) {
                int pbase = (px * NGRID + lc) * NBC + bc;
                for (int py = lc; py <= hc; ++py, pbase += NBC)
                    inc2_pos(pbase, cvec, rvec, kA, kB);
            }
            UPD2(cntA, bwA, WA, kA); UPD2(cntB, bwB, WB, kB);
        }
        if (a <= b) {
            for (int px = a; px <= b; ++px) {
                if (lr < lc) {
                    int pbase = (px * NGRID + lr) * NBC + bc;
                    for (int py = lr; py < a; ++py, pbase += NBC)
                        read2_pos(pbase, cvec, rvec, bwA, WA, BA, bwB, WB, BB);
                } else if (lc < lr) {
                    int kA = 0, kB = 0;
                    int pbase = (px * NGRID + lc) * NBC + bc;
                    for (int py = lc; py < a; ++py, pbase += NBC)
                        inc2_pos(pbase, cvec, rvec, kA, kB);
                    UPD2(cntA, bwA, WA, kA); UPD2(cntB, bwB, WB, kB);
                }
                {
                    int pbase = (px * NGRID + a) * NBC + bc;
                    for (int py = a; py <= b; ++py, pbase += NBC)
                        mixed2_pos(pbase, cvec, rvec, cntA, bwA, WA, BA, cntB, bwB, WB, BB, s_rcp);
                }
                if (hr > hc) {
                    int pbase = (px * NGRID + b + 1) * NBC + bc;
                    for (int py = b + 1; py <= hr; ++py, pbase += NBC)
                        read2_pos(pbase, cvec, rvec, bwA, WA, BA, bwB, WB, BB);
                } else if (hc > hr) {
                    int kA = 0, kB = 0;
                    int pbase = (px * NGRID + b + 1) * NBC + bc;
                    for (int py = b + 1; py <= hc; ++py, pbase += NBC)
                        inc2_pos(pbase, cvec, rvec, kA, kB);
                    UPD2(cntA, bwA, WA, kA); UPD2(cntB, bwB, WB, kB);
                }
            }
        }
        if (hc > hr) {
            for (int px = b + 1; px <= hc; ++px) {
                int pbase = (px * NGRID + lr) * NBC + bc;
                for (int py = lr; py <= hr; ++py, pbase += NBC)
                    read2_pos(pbase, cvec, rvec, bwA, WA, BA, bwB, WB, BB);
            }
        } else if (hr > hc) {
            int kA = 0, kB = 0;
            for (int px = b + 1; px <= hr; ++px) {
                int pbase = (px * NGRID + lc) * NBC + bc;
                for (int py = lc; py <= hc; ++py, pbase += NBC)
                    inc2_pos(pbase, cvec, rvec, kA, kB);
            }
            UPD2(cntA, bwA, WA, kA); UPD2(cntB, bwB, WB, kB);
        }
    }

    float* oplane = out + (size_t)bc * (HH * WW);
    oplane[pix0]     = (v0A + BA) * __frcp_rn(WA * (float)cntA);
    oplane[pix0 + 1] = (v0B + BB) * __frcp_rn(WB * (float)cntB);
}

// ============================================================
extern "C" void kernel_launch(void* const* d_in, const int* in_sizes, int n_in,
                              void* d_out, int out_size) {
    const float* images = (const float*)d_in[0];
    const float* Wp = (const float*)d_in[1];
    const float* bp = (const float*)d_in[2];
    const float* pe = (const float*)d_in[3];
    const float* Wb = (const float*)d_in[4];
    const float* bb = (const float*)d_in[5];
    float* out = (float*)d_out;

    int prep_items = 49 * 49 + NPK * 49;
    prep_kernel<<<(prep_items + 127) / 128, 128>>>(Wp, bp, pe, Wb, bb);
    simtopk_kernel<<<NUNIT / 8, 256>>>(images);
    gemm_kernel<<<NROW / 128, 128>>>();

    dim3 gg((HH * WW) / 16);
    dim3 bl(32, 8);
    gather_kernel<<<gg, bl>>>(images, out);
}

// round 15
// speedup vs baseline: 1.0430x; 1.0430x over previous
#include <cuda_runtime.h>
#include <cstdint>
#include <math.h>

// ---- problem constants ----
#define NPK   10
#define LLEN  14
#define EMB   128
#define HH    160
#define WW    160
#define NBC   32
#define NGRID 36
#define NPOS  (NGRID*NGRID)
#define NUNIT (NPOS*NBC)    // 41472
#define NROW  (NUNIT*NPK)   // 414720
#define SEV   0x07070707

// ---- static scratch ----
__device__ float g_patches[(size_t)NROW * 49];
__device__ float g_den[(size_t)NROW * 49];
__device__ int4  g_cp[NUNIT * 2];   // [2u]=x-bytes(10+2 pad 0xC8), [2u+1]=y-bytes
__device__ float g_Wc[49 * 52];
__device__ float g_bias[NPK * 49];

// ============================================================
// K0: fold projections, ILP-4 (R13-measured)
// ============================================================
__global__ void prep_kernel(const float* __restrict__ Wp, const float* __restrict__ bp,
                            const float* __restrict__ pe, const float* __restrict__ Wb,
                            const float* __restrict__ bb) {
    int i = blockIdx.x * blockDim.x + threadIdx.x;
    if (i < 49 * 49) {
        int q = i / 49, k = i % 49;
        float s0 = 0.0f, s1 = 0.0f, s2 = 0.0f, s3 = 0.0f;
        #pragma unroll 8
        for (int e = 0; e < EMB; e += 4) {
            s0 = fmaf(Wp[q * EMB + e],     Wb[(e)     * 49 + k], s0);
            s1 = fmaf(Wp[q * EMB + e + 1], Wb[(e + 1) * 49 + k], s1);
            s2 = fmaf(Wp[q * EMB + e + 2], Wb[(e + 2) * 49 + k], s2);
            s3 = fmaf(Wp[q * EMB + e + 3], Wb[(e + 3) * 49 + k], s3);
        }
        g_Wc[q * 52 + k] = (s0 + s1) + (s2 + s3);
    } else if (i < 49 * 49 + NPK * 49) {
        int j = i - 49 * 49;
        int n = j / 49, k = j % 49;
        float s0 = bb[k], s1 = 0.0f, s2 = 0.0f, s3 = 0.0f;
        #pragma unroll 8
        for (int e = 0; e < EMB; e += 4) {
            s0 = fmaf(bp[e]     + pe[n * EMB + e],     Wb[(e)     * 49 + k], s0);
            s1 = fmaf(bp[e + 1] + pe[n * EMB + e + 1], Wb[(e + 1) * 49 + k], s1);
            s2 = fmaf(bp[e + 2] + pe[n * EMB + e + 2], Wb[(e + 2) * 49 + k], s2);
            s3 = fmaf(bp[e + 3] + pe[n * EMB + e + 3], Wb[(e + 3) * 49 + k], s3);
        }
        g_bias[j] = (s0 + s1) + (s2 + s3);
    }
}

// ============================================================
// K1: sims + top-10 (REDUX, lax.top_k tie-break) + transposed
//     patches + byte-packed coords. (R13-measured)
// ============================================================
__global__ void __launch_bounds__(256) simtopk_kernel(const float* __restrict__ images) {
    __shared__ float swin_all[8][400];
    int wid = threadIdx.x >> 5, lane = threadIdx.x & 31;
    int unit = blockIdx.x * 8 + wid;
    float* swin = swin_all[wid];

    int p  = unit >> 5;
    int bc = unit & 31;
    int px = p / NGRID, py = p % NGRID;
    int x = px * 4, y = py * 4;
    int xb0 = x - 7; if (xb0 < 0) xb0 = 0;
    int yb0 = y - 7; if (yb0 < 0) yb0 = 0;
    int winW = x + 13 - xb0;
    int winH = y + 13 - yb0;

    const float* plane = images + (size_t)bc * (HH * WW);
    for (int t = lane; t < 400; t += 32)
        swin[t] = plane[(yb0 + t / 20) * WW + xb0 + (t % 20)];
    __syncwarp();

    int ry = y - yb0, rx = x - xb0;
    int r = lane >> 1, ox0 = (lane & 1) * 7;
    bool active = lane < 28;
    float acc[7];
    int flatbase;
    if (active) {
        #pragma unroll
        for (int o = 0; o < 7; o++) acc[o] = 0.0f;
        for (int a = 0; a < 7; a++) {
            float w[13];
            #pragma unroll
            for (int v = 0; v < 13; v++) w[v] = swin[(r + a) * 20 + ox0 + v];
            #pragma unroll
            for (int b = 0; b < 7; b++) {
                float rv = swin[(ry + a) * 20 + rx + b];
                #pragma unroll
                for (int o = 0; o < 7; o++) acc[o] = fmaf(w[o + b], rv, acc[o]);
            }
        }
        int maxr = winH - 7, maxc = winW - 7;
        #pragma unroll
        for (int o = 0; o < 7; o++)
            if (r > maxr || (ox0 + o) > maxc) acc[o] = -INFINITY;
        flatbase = r * LLEN + ox0;
    } else {
        #pragma unroll
        for (int o = 0; o < 7; o++) acc[o] = -INFINITY;
        flatbase = 1 << 20;
    }

    int lane_m7 = lane % 7, lane_d7 = lane / 7;
    int q32_m7 = (lane + 32) % 7, q32_d7 = (lane + 32) / 7;

    int xw0 = 0, xw1 = 0, xw2 = 0xC8C80000, yw0 = 0, yw1 = 0, yw2 = 0xC8C80000;

    for (int n = 0; n < NPK; n++) {
        float bv = acc[0]; int bo = 0;
        #pragma unroll
        for (int o = 1; o < 7; o++)
            if (acc[o] > bv) { bv = acc[o]; bo = o; }
        unsigned ub = __float_as_uint(bv);
        ub ^= (unsigned)(((int)ub >> 31)) | 0x80000000u;
        unsigned wmax = __reduce_max_sync(0xffffffffu, ub);
        int cand = (ub == wmax) ? (flatbase + bo) : 0x7fffffff;
        int bi = __reduce_min_sync(0xffffffffu, cand);

        if (active && bi >= flatbase && bi < flatbase + 7) acc[bi - flatbase] = -INFINITY;

        int oy = bi / LLEN, ox = bi - oy * LLEN;
        float* pout = g_patches + ((size_t)unit * NPK + n) * 49;
        pout[lane] = swin[(oy + lane_m7) * 20 + ox + lane_d7];
        if (lane < 17)
            pout[lane + 32] = swin[(oy + q32_m7) * 20 + ox + q32_d7];
        if (lane == 0) {
            int xb = oy + xb0, yb = ox + yb0;   // bug kept: x from row off, y from col off
            int sh = (n & 3) * 8;
            if (n < 4)      { xw0 |= xb << sh; yw0 |= yb << sh; }
            else if (n < 8) { xw1 |= xb << sh; yw1 |= yb << sh; }
            else            { xw2 |= xb << sh; yw2 |= yb << sh; }
        }
    }
    if (lane == 0) {
        g_cp[unit * 2]     = make_int4(xw0, xw1, xw2, 0);
        g_cp[unit * 2 + 1] = make_int4(yw0, yw1, yw2, 0);
    }
}

// ============================================================
// K2: den[row] = patches[row] @ Wc + bias[row % 10] (R13-measured)
// ============================================================
__global__ void __launch_bounds__(128) gemm_kernel() {
    __shared__ float s_pat[128 * 49];
    __shared__ float s_Wc[49 * 52];
    __shared__ float s_bias[NPK * 49];
    int t = threadIdx.x;
    size_t base = (size_t)blockIdx.x * 128 * 49;
    for (int i = t; i < 128 * 49; i += 128) s_pat[i] = g_patches[base + i];
    for (int i = t; i < 49 * 52;  i += 128) s_Wc[i]  = g_Wc[i];
    for (int i = t; i < NPK * 49; i += 128) s_bias[i] = g_bias[i];
    __syncthreads();

    int grow = blockIdx.x * 128 + t;
    int n = grow % NPK;
    float acc[49];
    #pragma unroll
    for (int k = 0; k < 49; k++) acc[k] = s_bias[n * 49 + k];
    for (int q = 0; q < 49; q++) {
        float pq = s_pat[t * 49 + q];
        #pragma unroll
        for (int k4 = 0; k4 < 12; k4++) {
            float4 w = *(const float4*)&s_Wc[q * 52 + k4 * 4];
            acc[k4 * 4 + 0] = fmaf(pq, w.x, acc[k4 * 4 + 0]);
            acc[k4 * 4 + 1] = fmaf(pq, w.y, acc[k4 * 4 + 1]);
            acc[k4 * 4 + 2] = fmaf(pq, w.z, acc[k4 * 4 + 2]);
            acc[k4 * 4 + 3] = fmaf(pq, w.w, acc[k4 * 4 + 3]);
        }
        acc[48] = fmaf(pq, s_Wc[q * 52 + 48], acc[48]);
    }
    __syncthreads();
    #pragma unroll
    for (int k = 0; k < 49; k++) s_pat[t * 49 + k] = acc[k];
    __syncthreads();
    for (int i = t; i < 128 * 49; i += 128) g_den[base + i] = s_pat[i];
}

// ============================================================
// K3: per-pixel gather (R13 segmented) + early-skip on merged
// masks (kills the 3 divergent loop regions on empty positions).
// Event order preserved exactly: word0->1->2, n ascending,
// read-before-inc at a shared step.
//   read at counter c : B = fma(d, W, B);  W *= (c+1)/c
//   k incs            : W *= c/(c+k)
//   final             : v = (v0 + B) * frcp(W * c_final)
// ============================================================
__device__ __forceinline__ int inc_count_word(int xw, int yw, int cvec, int rvec) {
    unsigned m = __vcmpltu4(__vsub4(rvec, xw), SEV) &
                 __vcmpltu4(__vsub4(cvec, yw), SEV);
    return __popc(m & 0x01010101u);
}

__device__ __forceinline__ int inc_pos(int pidx, int cvec, int rvec) {
    int4 xq = g_cp[pidx * 2];
    int4 yq = g_cp[pidx * 2 + 1];
    return inc_count_word(xq.x, yq.x, cvec, rvec) +
           inc_count_word(xq.y, yq.y, cvec, rvec) +
           inc_count_word(xq.z, yq.z, cvec, rvec);
}

__device__ __forceinline__ void read_pos(int pidx, int cvec, int rvec,
                                         float bw, float& W, float& B) {
    int4 xq = g_cp[pidx * 2];
    int4 yq = g_cp[pidx * 2 + 1];
    int xd0 = __vsub4(cvec, xq.x), yd0 = __vsub4(rvec, yq.x);
    int xd1 = __vsub4(cvec, xq.y), yd1 = __vsub4(rvec, yq.y);
    int xd2 = __vsub4(cvec, xq.z), yd2 = __vsub4(rvec, yq.z);
    unsigned m0 = __vcmpltu4(xd0, SEV) & __vcmpltu4(yd0, SEV);
    unsigned m1 = __vcmpltu4(xd1, SEV) & __vcmpltu4(yd1, SEV);
    unsigned m2 = __vcmpltu4(xd2, SEV) & __vcmpltu4(yd2, SEV);
    if ((m0 | m1 | m2) == 0u) return;
    int sbase = pidx * NPK;
    while (m0) {
        int sh = __ffs(m0) - 1;
        float d = g_den[(size_t)(sbase + (sh >> 3)) * 49 + ((yd0 >> sh) & 7) * 7 + ((xd0 >> sh) & 7)];
        B = fmaf(d, W, B);
        W *= bw;
        m0 &= ~(0xFFu << sh);
    }
    while (m1) {
        int sh = __ffs(m1) - 1;
        float d = g_den[(size_t)(sbase + 4 + (sh >> 3)) * 49 + ((yd1 >> sh) & 7) * 7 + ((xd1 >> sh) & 7)];
        B = fmaf(d, W, B);
        W *= bw;
        m1 &= ~(0xFFu << sh);
    }
    while (m2) {
        int sh = __ffs(m2) - 1;
        float d = g_den[(size_t)(sbase + 8 + (sh >> 3)) * 49 + ((yd2 >> sh) & 7) * 7 + ((xd2 >> sh) & 7)];
        B = fmaf(d, W, B);
        W *= bw;
        m2 &= ~(0xFFu << sh);
    }
}

__device__ __forceinline__ void mixed_word(int xw, int yw, int n0, int sbase,
                                           int cvec, int rvec,
                                           int& cnt, float& bw, float& W, float& B,
                                           const float* __restrict__ s_rcp) {
    int xdR = __vsub4(cvec, xw), ydR = __vsub4(rvec, yw);
    unsigned mR = __vcmpltu4(xdR, SEV) & __vcmpltu4(ydR, SEV);
    unsigned mI = __vcmpltu4(__vsub4(rvec, xw), SEV) &
                  __vcmpltu4(__vsub4(cvec, yw), SEV);
    unsigned mo = mR | mI;
    while (mo) {
        int sh = __ffs(mo) - 1;
        if ((mR >> sh) & 1) {
            int n = n0 + (sh >> 3);
            float d = g_den[(size_t)(sbase + n) * 49 + ((ydR >> sh) & 7) * 7 + ((xdR >> sh) & 7)];
            B = fmaf(d, W, B);
            W *= bw;
        }
        if ((mI >> sh) & 1) {
            W *= (1.0f - s_rcp[cnt + 1]);
            cnt++;
            bw = 1.0f + s_rcp[cnt];
        }
        mo &= ~(0xFFu << sh);
    }
}

__device__ __forceinline__ void mixed_pos(int pidx, int cvec, int rvec,
                                          int& cnt, float& bw, float& W, float& B,
                                          const float* __restrict__ s_rcp) {
    int4 xq = g_cp[pidx * 2];
    int4 yq = g_cp[pidx * 2 + 1];
    // quick reject: union of read+inc masks over all 3 words
    unsigned r0 = __vcmpltu4(__vsub4(cvec, xq.x), SEV) & __vcmpltu4(__vsub4(rvec, yq.x), SEV);
    unsigned r1 = __vcmpltu4(__vsub4(cvec, xq.y), SEV) & __vcmpltu4(__vsub4(rvec, yq.y), SEV);
    unsigned r2 = __vcmpltu4(__vsub4(cvec, xq.z), SEV) & __vcmpltu4(__vsub4(rvec, yq.z), SEV);
    unsigned i0 = __vcmpltu4(__vsub4(rvec, xq.x), SEV) & __vcmpltu4(__vsub4(cvec, yq.x), SEV);
    unsigned i1 = __vcmpltu4(__vsub4(rvec, xq.y), SEV) & __vcmpltu4(__vsub4(cvec, yq.y), SEV);
    unsigned i2 = __vcmpltu4(__vsub4(rvec, xq.z), SEV) & __vcmpltu4(__vsub4(cvec, yq.z), SEV);
    if ((r0 | r1 | r2 | i0 | i1 | i2) == 0u) return;
    int sbase = pidx * NPK;
    mixed_word(xq.x, yq.x, 0, sbase, cvec, rvec, cnt, bw, W, B, s_rcp);
    mixed_word(xq.y, yq.y, 4, sbase, cvec, rvec, cnt, bw, W, B, s_rcp);
    mixed_word(xq.z, yq.z, 8, sbase, cvec, rvec, cnt, bw, W, B, s_rcp);
}

__global__ void __launch_bounds__(256) gather_kernel(const float* __restrict__ images,
                                                     float* __restrict__ out) {
    __shared__ float s_rcp[512];
    {
        int t = threadIdx.y * 32 + threadIdx.x;
        for (int i = t; i < 512; i += 256) s_rcp[i] = __frcp_rn((float)i);  // 1/c
    }
    __syncthreads();

    int bc  = threadIdx.x;                 // lane = plane -> warp-uniform (r,c)
    int pix = blockIdx.x * 8 + threadIdx.y;
    int r = pix / WW, c = pix % WW;

    float v0 = images[(size_t)bc * (HH * WW) + pix];
    float v = v0;

    int lr = (r <= 19) ? 0 : ((r - 9) >> 2);
    int hr = (r + 7) >> 2; if (hr > 35) hr = 35;
    int lc = (c <= 19) ? 0 : ((c - 9) >> 2);
    int hc = (c + 7) >> 2; if (hc > 35) hc = 35;

    if (lr <= hr && lc <= hc) {
        int cvec = c * 0x01010101, rvec = r * 0x01010101;
        float W = 1.0f, B = 0.0f;
        int cnt = 1;

        if (hc < lr) {
            for (int px = lc; px <= hc; ++px) {
                int pbase = (px * NGRID + lr) * NBC + bc;
                for (int py = lr; py <= hr; ++py, pbase += NBC)
                    read_pos(pbase, cvec, rvec, 2.0f, W, B);
            }
        } else if (hr < lc) {
            int T = 0;
            for (int px = lr; px <= hr; ++px) {
                int pbase = (px * NGRID + lc) * NBC + bc;
                for (int py = lc; py <= hc; ++py, pbase += NBC)
                    T += inc_pos(pbase, cvec, rvec);
            }
            cnt = 1 + T;
            W = s_rcp[cnt];
            float bw = 1.0f + s_rcp[cnt];
            for (int px = lc; px <= hc; ++px) {
                int pbase = (px * NGRID + lr) * NBC + bc;
                for (int py = lr; py <= hr; ++py, pbase += NBC)
                    read_pos(pbase, cvec, rvec, bw, W, B);
            }
        } else {
            float bw = 2.0f;
            int a = max(lr, lc), b = min(hr, hc);

            if (lc < lr) {
                for (int px = lc; px < a; ++px) {
                    int pbase = (px * NGRID + lr) * NBC + bc;
                    for (int py = lr; py <= hr; ++py, pbase += NBC)
                        read_pos(pbase, cvec, rvec, bw, W, B);
                }
            } else if (lr < lc) {
                int k = 0;
                for (int px = lr; px < a; ++px) {
                    int pbase = (px * NGRID + lc) * NBC + bc;
                    for (int py = lc; py <= hc; ++py, pbase += NBC)
                        k += inc_pos(pbase, cvec, rvec);
                }
                if (k) { W *= (float)cnt * s_rcp[cnt + k]; cnt += k; bw = 1.0f + s_rcp[cnt]; }
            }
            for (int px = a; px <= b; ++px) {
                if (lr < lc) {
                    int pbase = (px * NGRID + lr) * NBC + bc;
                    for (int py = lr; py < a; ++py, pbase += NBC)
                        read_pos(pbase, cvec, rvec, bw, W, B);
                } else if (lc < lr) {
                    int k = 0;
                    int pbase = (px * NGRID + lc) * NBC + bc;
                    for (int py = lc; py < a; ++py, pbase += NBC)
                        k += inc_pos(pbase, cvec, rvec);
                    if (k) { W *= (float)cnt * s_rcp[cnt + k]; cnt += k; bw = 1.0f + s_rcp[cnt]; }
                }
                {
                    int pbase = (px * NGRID + a) * NBC + bc;
                    for (int py = a; py <= b; ++py, pbase += NBC)
                        mixed_pos(pbase, cvec, rvec, cnt, bw, W, B, s_rcp);
                }
                if (hr > hc) {
                    int pbase = (px * NGRID + b + 1) * NBC + bc;
                    for (int py = b + 1; py <= hr; ++py, pbase += NBC)
                        read_pos(pbase, cvec, rvec, bw, W, B);
                } else if (hc > hr) {
                    int k = 0;
                    int pbase = (px * NGRID + b + 1) * NBC + bc;
                    for (int py = b + 1; py <= hc; ++py, pbase += NBC)
                        k += inc_pos(pbase, cvec, rvec);
                    if (k) { W *= (float)cnt * s_rcp[cnt + k]; cnt += k; bw = 1.0f + s_rcp[cnt]; }
                }
            }
            if (hc > hr) {
                for (int px = b + 1; px <= hc; ++px) {
                    int pbase = (px * NGRID + lr) * NBC + bc;
                    for (int py = lr; py <= hr; ++py, pbase += NBC)
                        read_pos(pbase, cvec, rvec, bw, W, B);
                }
            } else if (hr > hc) {
                int k = 0;
                for (int px = b + 1; px <= hr; ++px) {
                    int pbase = (px * NGRID + lc) * NBC + bc;
                    for (int py = lc; py <= hc; ++py, pbase += NBC)
                        k += inc_pos(pbase, cvec, rvec);
                }
                if (k) { W *= (float)cnt * s_rcp[cnt + k]; cnt += k; }
            }
        }
        v = (v0 + B) * __frcp_rn(W * (float)cnt);
    }

    out[(size_t)bc * (HH * WW) + pix] = v;
}

// ============================================================
extern "C" void kernel_launch(void* const* d_in, const int* in_sizes, int n_in,
                              void* d_out, int out_size) {
    const float* images = (const float*)d_in[0];
    const float* Wp = (const float*)d_in[1];
    const float* bp = (const float*)d_in[2];
    const float* pe = (const float*)d_in[3];
    const float* Wb = (const float*)d_in[4];
    const float* bb = (const float*)d_in[5];
    float* out = (float*)d_out;

    int prep_items = 49 * 49 + NPK * 49;
    prep_kernel<<<(prep_items + 127) / 128, 128>>>(Wp, bp, pe, Wb, bb);
    simtopk_kernel<<<NUNIT / 8, 256>>>(images);
    gemm_kernel<<<NROW / 128, 128>>>();

    dim3 gg((HH * WW) / 8);
    dim3 bl(32, 8);
    gather_kernel<<<gg, bl>>>(images, out);
}

// round 16
// speedup vs baseline: 1.1135x; 1.0677x over previous
#include <cuda_runtime.h>
#include <cstdint>
#include <math.h>

// ---- problem constants ----
#define NPK   10
#define LLEN  14
#define EMB   128
#define HH    160
#define WW    160
#define NBC   32
#define NGRID 36
#define NPOS  (NGRID*NGRID)
#define NUNIT (NPOS*NBC)    // 41472
#define NROW  (NUNIT*NPK)   // 414720
#define SEV   0x07070707

// ---- static scratch ----
__device__ float g_patches[(size_t)NROW * 49];
__device__ float g_den[(size_t)NROW * 49];
__device__ int4  g_cp[NUNIT * 2];   // [2u]=x-bytes(10+2 pad 0xC8), [2u+1]=y-bytes
__device__ float g_Wc[49 * 52];
__device__ float g_bias[NPK * 49];

// ============================================================
// K0: fold projections, ILP-4 (R13-measured)
// ============================================================
__global__ void prep_kernel(const float* __restrict__ Wp, const float* __restrict__ bp,
                            const float* __restrict__ pe, const float* __restrict__ Wb,
                            const float* __restrict__ bb) {
    int i = blockIdx.x * blockDim.x + threadIdx.x;
    if (i < 49 * 49) {
        int q = i / 49, k = i % 49;
        float s0 = 0.0f, s1 = 0.0f, s2 = 0.0f, s3 = 0.0f;
        #pragma unroll 8
        for (int e = 0; e < EMB; e += 4) {
            s0 = fmaf(Wp[q * EMB + e],     Wb[(e)     * 49 + k], s0);
            s1 = fmaf(Wp[q * EMB + e + 1], Wb[(e + 1) * 49 + k], s1);
            s2 = fmaf(Wp[q * EMB + e + 2], Wb[(e + 2) * 49 + k], s2);
            s3 = fmaf(Wp[q * EMB + e + 3], Wb[(e + 3) * 49 + k], s3);
        }
        g_Wc[q * 52 + k] = (s0 + s1) + (s2 + s3);
    } else if (i < 49 * 49 + NPK * 49) {
        int j = i - 49 * 49;
        int n = j / 49, k = j % 49;
        float s0 = bb[k], s1 = 0.0f, s2 = 0.0f, s3 = 0.0f;
        #pragma unroll 8
        for (int e = 0; e < EMB; e += 4) {
            s0 = fmaf(bp[e]     + pe[n * EMB + e],     Wb[(e)     * 49 + k], s0);
            s1 = fmaf(bp[e + 1] + pe[n * EMB + e + 1], Wb[(e + 1) * 49 + k], s1);
            s2 = fmaf(bp[e + 2] + pe[n * EMB + e + 2], Wb[(e + 2) * 49 + k], s2);
            s3 = fmaf(bp[e + 3] + pe[n * EMB + e + 3], Wb[(e + 3) * 49 + k], s3);
        }
        g_bias[j] = (s0 + s1) + (s2 + s3);
    }
}

// ============================================================
// K1: sims + top-10 (REDUX, lax.top_k tie-break) + transposed
//     patches + byte-packed coords. (R13-measured)
// ============================================================
__global__ void __launch_bounds__(256) simtopk_kernel(const float* __restrict__ images) {
    __shared__ float swin_all[8][400];
    int wid = threadIdx.x >> 5, lane = threadIdx.x & 31;
    int unit = blockIdx.x * 8 + wid;
    float* swin = swin_all[wid];

    int p  = unit >> 5;
    int bc = unit & 31;
    int px = p / NGRID, py = p % NGRID;
    int x = px * 4, y = py * 4;
    int xb0 = x - 7; if (xb0 < 0) xb0 = 0;
    int yb0 = y - 7; if (yb0 < 0) yb0 = 0;
    int winW = x + 13 - xb0;
    int winH = y + 13 - yb0;

    const float* plane = images + (size_t)bc * (HH * WW);
    for (int t = lane; t < 400; t += 32)
        swin[t] = plane[(yb0 + t / 20) * WW + xb0 + (t % 20)];
    __syncwarp();

    int ry = y - yb0, rx = x - xb0;
    int r = lane >> 1, ox0 = (lane & 1) * 7;
    bool active = lane < 28;
    float acc[7];
    int flatbase;
    if (active) {
        #pragma unroll
        for (int o = 0; o < 7; o++) acc[o] = 0.0f;
        for (int a = 0; a < 7; a++) {
            float w[13];
            #pragma unroll
            for (int v = 0; v < 13; v++) w[v] = swin[(r + a) * 20 + ox0 + v];
            #pragma unroll
            for (int b = 0; b < 7; b++) {
                float rv = swin[(ry + a) * 20 + rx + b];
                #pragma unroll
                for (int o = 0; o < 7; o++) acc[o] = fmaf(w[o + b], rv, acc[o]);
            }
        }
        int maxr = winH - 7, maxc = winW - 7;
        #pragma unroll
        for (int o = 0; o < 7; o++)
            if (r > maxr || (ox0 + o) > maxc) acc[o] = -INFINITY;
        flatbase = r * LLEN + ox0;
    } else {
        #pragma unroll
        for (int o = 0; o < 7; o++) acc[o] = -INFINITY;
        flatbase = 1 << 20;
    }

    int lane_m7 = lane % 7, lane_d7 = lane / 7;
    int q32_m7 = (lane + 32) % 7, q32_d7 = (lane + 32) / 7;

    int xw0 = 0, xw1 = 0, xw2 = 0xC8C80000, yw0 = 0, yw1 = 0, yw2 = 0xC8C80000;

    for (int n = 0; n < NPK; n++) {
        float bv = acc[0]; int bo = 0;
        #pragma unroll
        for (int o = 1; o < 7; o++)
            if (acc[o] > bv) { bv = acc[o]; bo = o; }
        unsigned ub = __float_as_uint(bv);
        ub ^= (unsigned)(((int)ub >> 31)) | 0x80000000u;
        unsigned wmax = __reduce_max_sync(0xffffffffu, ub);
        int cand = (ub == wmax) ? (flatbase + bo) : 0x7fffffff;
        int bi = __reduce_min_sync(0xffffffffu, cand);

        if (active && bi >= flatbase && bi < flatbase + 7) acc[bi - flatbase] = -INFINITY;

        int oy = bi / LLEN, ox = bi - oy * LLEN;
        float* pout = g_patches + ((size_t)unit * NPK + n) * 49;
        pout[lane] = swin[(oy + lane_m7) * 20 + ox + lane_d7];
        if (lane < 17)
            pout[lane + 32] = swin[(oy + q32_m7) * 20 + ox + q32_d7];
        if (lane == 0) {
            int xb = oy + xb0, yb = ox + yb0;   // bug kept: x from row off, y from col off
            int sh = (n & 3) * 8;
            if (n < 4)      { xw0 |= xb << sh; yw0 |= yb << sh; }
            else if (n < 8) { xw1 |= xb << sh; yw1 |= yb << sh; }
            else            { xw2 |= xb << sh; yw2 |= yb << sh; }
        }
    }
    if (lane == 0) {
        g_cp[unit * 2]     = make_int4(xw0, xw1, xw2, 0);
        g_cp[unit * 2 + 1] = make_int4(yw0, yw1, yw2, 0);
    }
}

// ============================================================
// K2: den[row] = patches[row] @ Wc + bias[row % 10]
// SPLIT-ROW: 2 threads per row (cols [0,24) / [24,49)), 256-thread
// blocks, same q-ascending per-column order -> bitwise-identical.
// ============================================================
__global__ void __launch_bounds__(256) gemm_kernel() {
    __shared__ float s_pat[128 * 49];
    __shared__ float s_Wc[49 * 52];
    __shared__ float s_bias[NPK * 49];
    int t = threadIdx.x;
    size_t base = (size_t)blockIdx.x * 128 * 49;
    for (int i = t; i < 128 * 49; i += 256) s_pat[i] = g_patches[base + i];
    for (int i = t; i < 49 * 52;  i += 256) s_Wc[i]  = g_Wc[i];
    for (int i = t; i < NPK * 49; i += 256) s_bias[i] = g_bias[i];
    __syncthreads();

    int rloc = t >> 1;                 // 0..127 row within block
    int half = t & 1;
    int k0 = half ? 24 : 0;
    int grow = blockIdx.x * 128 + rloc;
    int n = grow % NPK;

    float acc[25];
    #pragma unroll
    for (int k = 0; k < 24; k++) acc[k] = s_bias[n * 49 + k0 + k];
    if (half) acc[24] = s_bias[n * 49 + 48];

    for (int q = 0; q < 49; q++) {
        float pq = s_pat[rloc * 49 + q];      // 2-lane broadcast
        #pragma unroll
        for (int k4 = 0; k4 < 6; k4++) {
            float4 w = *(const float4*)&s_Wc[q * 52 + k0 + k4 * 4];
            acc[k4 * 4 + 0] = fmaf(pq, w.x, acc[k4 * 4 + 0]);
            acc[k4 * 4 + 1] = fmaf(pq, w.y, acc[k4 * 4 + 1]);
            acc[k4 * 4 + 2] = fmaf(pq, w.z, acc[k4 * 4 + 2]);
            acc[k4 * 4 + 3] = fmaf(pq, w.w, acc[k4 * 4 + 3]);
        }
        if (half) acc[24] = fmaf(pq, s_Wc[q * 52 + 48], acc[24]);
    }
    __syncthreads();
    #pragma unroll
    for (int k = 0; k < 24; k++) s_pat[rloc * 49 + k0 + k] = acc[k];
    if (half) s_pat[rloc * 49 + 48] = acc[24];
    __syncthreads();
    for (int i = t; i < 128 * 49; i += 256) g_den[base + i] = s_pat[i];
}

// ============================================================
// K3: per-pixel gather (R13-exact, measured 189.7us): segmented
// forward walk, affine (W,B):
//   read at counter c : B = fma(d, W, B);  W *= (c+1)/c
//   k incs            : W *= c/(c+k)
//   final             : v = (v0 + B) * frcp(W * c_final)
// ============================================================
__device__ __forceinline__ int inc_count_word(int xw, int yw, int cvec, int rvec) {
    unsigned m = __vcmpltu4(__vsub4(rvec, xw), SEV) &
                 __vcmpltu4(__vsub4(cvec, yw), SEV);
    return __popc(m & 0x01010101u);
}

__device__ __forceinline__ int inc_pos(int pidx, int cvec, int rvec) {
    int4 xq = g_cp[pidx * 2];
    int4 yq = g_cp[pidx * 2 + 1];
    return inc_count_word(xq.x, yq.x, cvec, rvec) +
           inc_count_word(xq.y, yq.y, cvec, rvec) +
           inc_count_word(xq.z, yq.z, cvec, rvec);
}

__device__ __forceinline__ void read_word(int xw, int yw, int n0, int sbase,
                                          int cvec, int rvec, float bw,
                                          float& W, float& B) {
    int xd = __vsub4(cvec, xw), yd = __vsub4(rvec, yw);
    unsigned m = __vcmpltu4(xd, SEV) & __vcmpltu4(yd, SEV);
    while (m) {
        int sh = __ffs(m) - 1;
        int n = n0 + (sh >> 3);
        int didx = ((yd >> sh) & 7) * 7 + ((xd >> sh) & 7);
        float d = g_den[(size_t)(sbase + n) * 49 + didx];
        B = fmaf(d, W, B);
        W *= bw;
        m &= ~(0xFFu << sh);
    }
}

__device__ __forceinline__ void read_pos(int pidx, int cvec, int rvec,
                                         float bw, float& W, float& B) {
    int4 xq = g_cp[pidx * 2];
    int4 yq = g_cp[pidx * 2 + 1];
    int sbase = pidx * NPK;
    read_word(xq.x, yq.x, 0, sbase, cvec, rvec, bw, W, B);
    read_word(xq.y, yq.y, 4, sbase, cvec, rvec, bw, W, B);
    read_word(xq.z, yq.z, 8, sbase, cvec, rvec, bw, W, B);
}

__device__ __forceinline__ void mixed_word(int xw, int yw, int n0, int sbase,
                                           int cvec, int rvec,
                                           int& cnt, float& bw, float& W, float& B,
                                           const float* __restrict__ s_rcp) {
    int xdR = __vsub4(cvec, xw), ydR = __vsub4(rvec, yw);
    unsigned mR = __vcmpltu4(xdR, SEV) & __vcmpltu4(ydR, SEV);
    unsigned mI = __vcmpltu4(__vsub4(rvec, xw), SEV) &
                  __vcmpltu4(__vsub4(cvec, yw), SEV);
    unsigned mo = mR | mI;
    while (mo) {
        int sh = __ffs(mo) - 1;
        if ((mR >> sh) & 1) {
            int n = n0 + (sh >> 3);
            int didx = ((ydR >> sh) & 7) * 7 + ((xdR >> sh) & 7);
            float d = g_den[(size_t)(sbase + n) * 49 + didx];
            B = fmaf(d, W, B);
            W *= bw;
        }
        if ((mI >> sh) & 1) {
            W *= (1.0f - s_rcp[cnt + 1]);
            cnt++;
            bw = 1.0f + s_rcp[cnt];
        }
        mo &= ~(0xFFu << sh);
    }
}

__device__ __forceinline__ void mixed_pos(int pidx, int cvec, int rvec,
                                          int& cnt, float& bw, float& W, float& B,
                                          const float* __restrict__ s_rcp) {
    int4 xq = g_cp[pidx * 2];
    int4 yq = g_cp[pidx * 2 + 1];
    int sbase = pidx * NPK;
    mixed_word(xq.x, yq.x, 0, sbase, cvec, rvec, cnt, bw, W, B, s_rcp);
    mixed_word(xq.y, yq.y, 4, sbase, cvec, rvec, cnt, bw, W, B, s_rcp);
    mixed_word(xq.z, yq.z, 8, sbase, cvec, rvec, cnt, bw, W, B, s_rcp);
}

__global__ void __launch_bounds__(256) gather_kernel(const float* __restrict__ images,
                                                     float* __restrict__ out) {
    __shared__ float s_rcp[512];
    {
        int t = threadIdx.y * 32 + threadIdx.x;
        for (int i = t; i < 512; i += 256) s_rcp[i] = __frcp_rn((float)i);  // 1/c
    }
    __syncthreads();

    int bc  = threadIdx.x;                 // lane = plane -> warp-uniform (r,c)
    int pix = blockIdx.x * 8 + threadIdx.y;
    int r = pix / WW, c = pix % WW;

    float v0 = images[(size_t)bc * (HH * WW) + pix];
    float v = v0;

    int lr = (r <= 19) ? 0 : ((r - 9) >> 2);
    int hr = (r + 7) >> 2; if (hr > 35) hr = 35;
    int lc = (c <= 19) ? 0 : ((c - 9) >> 2);
    int hc = (c + 7) >> 2; if (hc > 35) hc = 35;

    if (lr <= hr && lc <= hc) {
        int cvec = c * 0x01010101, rvec = r * 0x01010101;
        float W = 1.0f, B = 0.0f;
        int cnt = 1;

        if (hc < lr) {
            for (int px = lc; px <= hc; ++px) {
                int pbase = (px * NGRID + lr) * NBC + bc;
                for (int py = lr; py <= hr; ++py, pbase += NBC)
                    read_pos(pbase, cvec, rvec, 2.0f, W, B);
            }
        } else if (hr < lc) {
            int T = 0;
            for (int px = lr; px <= hr; ++px) {
                int pbase = (px * NGRID + lc) * NBC + bc;
                for (int py = lc; py <= hc; ++py, pbase += NBC)
                    T += inc_pos(pbase, cvec, rvec);
            }
            cnt = 1 + T;
            W = s_rcp[cnt];
            float bw = 1.0f + s_rcp[cnt];
            for (int px = lc; px <= hc; ++px) {
                int pbase = (px * NGRID + lr) * NBC + bc;
                for (int py = lr; py <= hr; ++py, pbase += NBC)
                    read_pos(pbase, cvec, rvec, bw, W, B);
            }
        } else {
            float bw = 2.0f;
            int a = max(lr, lc), b = min(hr, hc);

            if (lc < lr) {
                for (int px = lc; px < a; ++px) {
                    int pbase = (px * NGRID + lr) * NBC + bc;
                    for (int py = lr; py <= hr; ++py, pbase += NBC)
                        read_pos(pbase, cvec, rvec, bw, W, B);
                }
            } else if (lr < lc) {
                int k = 0;
                for (int px = lr; px < a; ++px) {
                    int pbase = (px * NGRID + lc) * NBC + bc;
                    for (int py = lc; py <= hc; ++py, pbase += NBC)
                        k += inc_pos(pbase, cvec, rvec);
                }
                if (k) { W *= (float)cnt * s_rcp[cnt + k]; cnt += k; bw = 1.0f + s_rcp[cnt]; }
            }
            for (int px = a; px <= b; ++px) {
                if (lr < lc) {
                    int pbase = (px * NGRID + lr) * NBC + bc;
                    for (int py = lr; py < a; ++py, pbase += NBC)
                        read_pos(pbase, cvec, rvec, bw, W, B);
                } else if (lc < lr) {
                    int k = 0;
                    int pbase = (px * NGRID + lc) * NBC + bc;
                    for (int py = lc; py < a; ++py, pbase += NBC)
                        k += inc_pos(pbase, cvec, rvec);
                    if (k) { W *= (float)cnt * s_rcp[cnt + k]; cnt += k; bw = 1.0f + s_rcp[cnt]; }
                }
                {
                    int pbase = (px * NGRID + a) * NBC + bc;
                    for (int py = a; py <= b; ++py, pbase += NBC)
                        mixed_pos(pbase, cvec, rvec, cnt, bw, W, B, s_rcp);
                }
                if (hr > hc) {
                    int pbase = (px * NGRID + b + 1) * NBC + bc;
                    for (int py = b + 1; py <= hr; ++py, pbase += NBC)
                        read_pos(pbase, cvec, rvec, bw, W, B);
                } else if (hc > hr) {
                    int k = 0;
                    int pbase = (px * NGRID + b + 1) * NBC + bc;
                    for (int py = b + 1; py <= hc; ++py, pbase += NBC)
                        k += inc_pos(pbase, cvec, rvec);
                    if (k) { W *= (float)cnt * s_rcp[cnt + k]; cnt += k; bw = 1.0f + s_rcp[cnt]; }
                }
            }
            if (hc > hr) {
                for (int px = b + 1; px <= hc; ++px) {
                    int pbase = (px * NGRID + lr) * NBC + bc;
                    for (int py = lr; py <= hr; ++py, pbase += NBC)
                        read_pos(pbase, cvec, rvec, bw, W, B);
                }
            } else if (hr > hc) {
                int k = 0;
                for (int px = b + 1; px <= hr; ++px) {
                    int pbase = (px * NGRID + lc) * NBC + bc;
                    for (int py = lc; py <= hc; ++py, pbase += NBC)
                        k += inc_pos(pbase, cvec, rvec);
                }
                if (k) { W *= (float)cnt * s_rcp[cnt + k]; cnt += k; }
            }
        }
        v = (v0 + B) * __frcp_rn(W * (float)cnt);
    }

    out[(size_t)bc * (HH * WW) + pix] = v;
}

// ============================================================
extern "C" void kernel_launch(void* const* d_in, const int* in_sizes, int n_in,
                              void* d_out, int out_size) {
    const float* images = (const float*)d_in[0];
    const float* Wp = (const float*)d_in[1];
    const float* bp = (const float*)d_in[2];
    const float* pe = (const float*)d_in[3];
    const float* Wb = (const float*)d_in[4];
    const float* bb = (const float*)d_in[5];
    float* out = (float*)d_out;

    int prep_items = 49 * 49 + NPK * 49;
    prep_kernel<<<(prep_items + 127) / 128, 128>>>(Wp, bp, pe, Wb, bb);
    simtopk_kernel<<<NUNIT / 8, 256>>>(images);
    gemm_kernel<<<NROW / 128, 256>>>();

    dim3 gg((HH * WW) / 8);
    dim3 bl(32, 8);
    gather_kernel<<<gg, bl>>>(images, out);
}